// round 1
// baseline (speedup 1.0000x reference)
#include <cuda_runtime.h>

// Problem constants
#define B_   8
#define N_   1024
#define D_   512
#define C_   1024
#define Q_   8
#define M_   (B_ * N_)      // 8192 rows
#define D4_  (D_ / 4)       // 128 float4 per row

// GEMM tile config
#define BM 64
#define BN 128
#define BK 32

// Output layout (all float32): [quantized_out M*D][indices M*Q][losses Q]
#define OUT_IDX_OFF  ((size_t)M_ * D_)
#define OUT_LOSS_OFF ((size_t)M_ * D_ + (size_t)M_ * Q_)

// Scratch (allocation-free: __device__ globals)
__device__ float g_residual[M_ * D_];   // 16.8 MB
__device__ float g_e2[Q_ * C_];
__device__ float g_loss[Q_];

// ---------------------------------------------------------------------------
// init: residual = x, zero loss accumulators
// ---------------------------------------------------------------------------
__global__ void init_kernel(const float4* __restrict__ x) {
    const int n4 = M_ * D_ / 4;
    float4* r4 = (float4*)g_residual;
    for (int i = blockIdx.x * blockDim.x + threadIdx.x; i < n4;
         i += gridDim.x * blockDim.x)
        r4[i] = x[i];
    if (blockIdx.x == 0 && threadIdx.x < Q_) g_loss[threadIdx.x] = 0.f;
}

// ---------------------------------------------------------------------------
// e2: ||codebook[q][c]||^2 for all 8 codebooks (one warp per row)
// ---------------------------------------------------------------------------
__global__ void e2_kernel(const float* __restrict__ cbs) {
    const int warp = (blockIdx.x * blockDim.x + threadIdx.x) >> 5;
    const int lane = threadIdx.x & 31;
    if (warp >= Q_ * C_) return;
    const float* row = cbs + (size_t)warp * D_;
    float s = 0.f;
#pragma unroll
    for (int i = 0; i < D_ / 32; i++) {
        float v = row[lane + 32 * i];
        s = fmaf(v, v, s);
    }
#pragma unroll
    for (int o = 16; o > 0; o >>= 1) s += __shfl_xor_sync(0xffffffffu, s, o);
    if (lane == 0) g_e2[warp] = s;
}

// ---------------------------------------------------------------------------
// Fused layer: tiled GEMM (residual . codebook^T) -> running argmin per row ->
// gather winner, update residual in place, accumulate loss, emit indices.
// Grid: M_/BM = 128 blocks x 256 threads.
// ---------------------------------------------------------------------------
__global__ __launch_bounds__(256) void vq_layer_kernel(
    const float* __restrict__ cb,     // this layer's codebook [C_][D_]
    float* __restrict__ idx_out,      // d_out + OUT_IDX_OFF (or null)
    int q)
{
    __shared__ float As[BK][BM + 1];   // +1 pad: conflict-free transposed STS/LDS
    __shared__ float Bs[BK][BN + 1];
    __shared__ float e2s[C_];
    __shared__ float redv[BM][16];
    __shared__ int   redi[BM][16];
    __shared__ int   sidx[BM];
    __shared__ float sred[256];

    const int t  = threadIdx.x;
    const int tm = t & 15;     // row group: rows tm + 16*r
    const int tn = t >> 4;     // col group: cols tn + 16*s
    const int bm0 = blockIdx.x * BM;

    const float* e2 = g_e2 + q * C_;
    for (int i = t; i < C_; i += 256) e2s[i] = e2[i];

    float best[4];
    int   bidx[4];
#pragma unroll
    for (int r = 0; r < 4; r++) { best[r] = 3.4e38f; bidx[r] = 0; }

    float acc[4][8];
#pragma unroll
    for (int r = 0; r < 4; r++)
#pragma unroll
        for (int s = 0; s < 8; s++) acc[r][s] = 0.f;

    float ra[8], rb[16];
    const float* Ag = g_residual + (size_t)bm0 * D_;

    for (int cc = 0; cc < C_ / BN; cc++) {
        const int c0 = cc * BN;
        const float* Bg = cb + (size_t)c0 * D_;

        // prefetch k-chunk 0 into registers
#pragma unroll
        for (int u = 0; u < 8; u++) {
            int i = t + 256 * u;
            ra[u] = Ag[(i >> 5) * D_ + (i & 31)];
        }
#pragma unroll
        for (int u = 0; u < 16; u++) {
            int i = t + 256 * u;
            rb[u] = Bg[(i >> 5) * D_ + (i & 31)];
        }

        for (int kt = 0; kt < D_ / BK; kt++) {
            __syncthreads();
            // transposed store (k-major) — pad makes this conflict-free
#pragma unroll
            for (int u = 0; u < 8; u++) {
                int i = t + 256 * u;
                As[i & 31][i >> 5] = ra[u];
            }
#pragma unroll
            for (int u = 0; u < 16; u++) {
                int i = t + 256 * u;
                Bs[i & 31][i >> 5] = rb[u];
            }
            __syncthreads();

            // prefetch next k-chunk while computing this one
            if (kt + 1 < D_ / BK) {
                const int k0 = (kt + 1) * BK;
#pragma unroll
                for (int u = 0; u < 8; u++) {
                    int i = t + 256 * u;
                    ra[u] = Ag[(i >> 5) * D_ + k0 + (i & 31)];
                }
#pragma unroll
                for (int u = 0; u < 16; u++) {
                    int i = t + 256 * u;
                    rb[u] = Bg[(i >> 5) * D_ + k0 + (i & 31)];
                }
            }

#pragma unroll
            for (int kk = 0; kk < BK; kk++) {
                float a[4], b[8];
#pragma unroll
                for (int r = 0; r < 4; r++) a[r] = As[kk][tm + 16 * r];
#pragma unroll
                for (int s = 0; s < 8; s++) b[s] = Bs[kk][tn + 16 * s];
#pragma unroll
                for (int r = 0; r < 4; r++)
#pragma unroll
                    for (int s = 0; s < 8; s++)
                        acc[r][s] = fmaf(a[r], b[s], acc[r][s]);
            }
        }

        // fold chunk into running min (ascending c + strict < => first-min)
#pragma unroll
        for (int s = 0; s < 8; s++) {
            int c = c0 + tn + 16 * s;
            float e = e2s[c];
#pragma unroll
            for (int r = 0; r < 4; r++) {
                float d = fmaf(-2.f, acc[r][s], e);
                if (d < best[r]) { best[r] = d; bidx[r] = c; }
                acc[r][s] = 0.f;
            }
        }
    }

    // cross-thread reduction: 16 col-groups share each row
#pragma unroll
    for (int r = 0; r < 4; r++) {
        redv[tm + 16 * r][tn] = best[r];
        redi[tm + 16 * r][tn] = bidx[r];
    }
    __syncthreads();
    if (t < BM) {
        float bv = redv[t][0];
        int   bi = redi[t][0];
#pragma unroll
        for (int j = 1; j < 16; j++) {
            float v = redv[t][j];
            int   i2 = redi[t][j];
            if (v < bv || (v == bv && i2 < bi)) { bv = v; bi = i2; }
        }
        sidx[t] = bi;
        if (idx_out)
            idx_out[(size_t)(bm0 + t) * Q_ + q] = (float)bi;
    }
    __syncthreads();

    // epilogue: residual -= codebook[idx]; loss += ||new residual||^2
    float4* R4 = (float4*)g_residual + (size_t)bm0 * D4_;
    const float4* C4 = (const float4*)cb;
    float sq = 0.f;
    for (int i = t; i < BM * D4_; i += 256) {
        int row = i >> 7;
        int j   = i & 127;
        int idx = sidx[row];
        float4 rv = R4[row * D4_ + j];
        float4 cv = C4[(size_t)idx * D4_ + j];
        rv.x -= cv.x; rv.y -= cv.y; rv.z -= cv.z; rv.w -= cv.w;
        R4[row * D4_ + j] = rv;
        sq = fmaf(rv.x, rv.x, sq);
        sq = fmaf(rv.y, rv.y, sq);
        sq = fmaf(rv.z, rv.z, sq);
        sq = fmaf(rv.w, rv.w, sq);
    }
    sred[t] = sq;
    __syncthreads();
    for (int o = 128; o > 0; o >>= 1) {
        if (t < o) sred[t] += sred[t + o];
        __syncthreads();
    }
    if (t == 0) atomicAdd(&g_loss[q], sred[0]);
}

// ---------------------------------------------------------------------------
// final: quantized_out = x - residual_final; write losses
// ---------------------------------------------------------------------------
__global__ void final_kernel(const float4* __restrict__ x,
                             float* __restrict__ out, int write_extra) {
    const int n4 = M_ * D_ / 4;
    float4* o4 = (float4*)out;
    const float4* r4 = (const float4*)g_residual;
    for (int i = blockIdx.x * blockDim.x + threadIdx.x; i < n4;
         i += gridDim.x * blockDim.x) {
        float4 xv = x[i], rv = r4[i];
        float4 ov;
        ov.x = xv.x - rv.x; ov.y = xv.y - rv.y;
        ov.z = xv.z - rv.z; ov.w = xv.w - rv.w;
        o4[i] = ov;
    }
    if (write_extra && blockIdx.x == 0 && threadIdx.x < Q_)
        out[OUT_LOSS_OFF + threadIdx.x] =
            g_loss[threadIdx.x] * (1.0f / ((float)M_ * (float)D_));
}

// ---------------------------------------------------------------------------
extern "C" void kernel_launch(void* const* d_in, const int* in_sizes, int n_in,
                              void* d_out, int out_size) {
    const float* x   = (const float*)d_in[0];
    const float* cbs = (const float*)d_in[1];
    float* out = (float*)d_out;

    const int full = (int)(OUT_LOSS_OFF + Q_);
    const int write_extra = (out_size >= full) ? 1 : 0;
    float* idx_out = write_extra ? out + OUT_IDX_OFF : nullptr;

    init_kernel<<<512, 256>>>((const float4*)x);
    e2_kernel<<<(Q_ * C_ * 32) / 256, 256>>>(cbs);
    for (int q = 0; q < Q_; q++)
        vq_layer_kernel<<<M_ / BM, 256>>>(cbs + (size_t)q * C_ * D_,
                                          idx_out, q);
    final_kernel<<<512, 256>>>((const float4*)x, out, write_extra);
}